// round 17
// baseline (speedup 1.0000x reference)
#include <cuda_runtime.h>
#include <cuda_bf16.h>
#include <cstdint>

// Problem constants (B=2, S=2048, D=512, K=64)
#define PB 2
#define PS 2048
#define PD 512
#define PK 64
#define MT (PB * PS)   // 4096 rows total

// ---------------------------------------------------------------------------
// Scratch (device globals — no allocation allowed)
// ---------------------------------------------------------------------------
__device__ __align__(16) __nv_bfloat16 g_x_bf[MT * PD];     // bf16(x)
__device__ __align__(16) __nv_bfloat16 g_z_bf[MT * PD];     // bf16(z = x @ Wc^T)
__device__ __align__(16) __nv_bfloat16 g_wo_hi[PD * PD];
__device__ __align__(16) __nv_bfloat16 g_wo_lo[PD * PD];
__device__ __align__(16) __nv_bfloat16 g_wit_hi[PD * PD];   // Wi^T split
__device__ __align__(16) __nv_bfloat16 g_wit_lo[PD * PD];
__device__ __align__(16) __nv_bfloat16 g_wc_bf[PD * PD];    // Wc = Wo @ Wi (bf16)

// ---------------------------------------------------------------------------
// PTX helpers (sm_80/sm_100-level only — harness compiles via compute_103 PTX,
// which rejects 'a'-gated tcgen05/TMEM; f32x2 packed math is plain sm_100+)
// ---------------------------------------------------------------------------
__device__ __forceinline__ uint32_t smem_u32(const void* p) {
    uint32_t a;
    asm("{ .reg .u64 t; cvta.to.shared.u64 t, %1; cvt.u32.u64 %0, t; }" : "=r"(a) : "l"(p));
    return a;
}

#define LDSM4(r, addr) \
    asm volatile("ldmatrix.sync.aligned.m8n8.x4.shared.b16 {%0,%1,%2,%3}, [%4];" \
                 : "=r"((r)[0]), "=r"((r)[1]), "=r"((r)[2]), "=r"((r)[3]) : "r"(addr))

#define MMA16816(d, a, b0, b1) \
    asm volatile("mma.sync.aligned.m16n8k16.row.col.f32.bf16.bf16.f32 " \
                 "{%0,%1,%2,%3}, {%4,%5,%6,%7}, {%8,%9}, {%0,%1,%2,%3};" \
                 : "+f"((d)[0]), "+f"((d)[1]), "+f"((d)[2]), "+f"((d)[3]) \
                 : "r"((a)[0]), "r"((a)[1]), "r"((a)[2]), "r"((a)[3]), "r"(b0), "r"(b1))

#define CP16(dst, src) \
    asm volatile("cp.async.cg.shared.global [%0], [%1], 16;" :: "r"(dst), "l"(src))
#define CP_COMMIT()  asm volatile("cp.async.commit_group;" ::: "memory")
#define CP_WAIT(N)   asm volatile("cp.async.wait_group %0;" :: "n"(N) : "memory")

// Packed bf16x2-word -> f32x2 convert + packed FMA:  acc(f32x2) += wk2 * {lo,hi}
#define CVT_FMA2(acc, u, wk2) \
    asm("{\n\t" \
        ".reg .b32 lo, hi;\n\t" \
        ".reg .b64 val;\n\t" \
        "shl.b32 lo, %1, 16;\n\t" \
        "and.b32 hi, %1, 0xFFFF0000;\n\t" \
        "mov.b64 val, {lo, hi};\n\t" \
        "fma.rn.f32x2 %0, %2, val, %0;\n\t" \
        "}" : "+l"(acc) : "r"(u), "l"(wk2))

// ---------------------------------------------------------------------------
// Common GEMM geometry (R13-proven): tile 128x64, BK=32, 8 warps (4m x 2n)
// smem row = 64B; swizzle u' = u ^ ((row>>1)&3)
// ---------------------------------------------------------------------------
#define GBM 128
#define GBN 64
#define GBK 32
#define NITER (PD / GBK)       // 16
#define STAGES 4
#define ATILEB (128 * 64)      // 8192 B
#define BTILEB (64 * 64)       // 4096 B
#define STAGEB (ATILEB + BTILEB)        // 12288 B
#define GEMM_SMEM (STAGES * STAGEB)     // 49152 B

__device__ __forceinline__ uint32_t swz(int row, int u) {
    return (uint32_t)(row * 64 + ((u ^ ((row >> 1) & 3)) * 16));
}

// ---------------------------------------------------------------------------
// Main GEMM (NT): C[m,n] = sum_k A[m,k]*B[n,k], bf16 in, bf16 out (z = x@Wc^T)
// ---------------------------------------------------------------------------
__global__ __launch_bounds__(256, 2)
void mma_gemm_kernel(const __nv_bfloat16* __restrict__ A,
                     const __nv_bfloat16* __restrict__ B,
                     __nv_bfloat16* __restrict__ Cb)
{
    extern __shared__ __align__(128) char sm[];
    const uint32_t sbase = smem_u32(sm);

    const int tid  = threadIdx.x;
    const int lane = tid & 31;
    const int wid  = tid >> 5;
    const int warpM = (wid & 3) * 32;
    const int warpN = (wid >> 2) * 32;
    const int blockM = blockIdx.y * GBM;
    const int blockN = blockIdx.x * GBN;

    const int arow = tid >> 1;
    const int au   = (tid & 1) * 2;
    const uint32_t acd0 = swz(arow, au);
    const uint32_t acd1 = swz(arow, au + 1);
    const size_t aoff = (size_t)(blockM + arow) * PD + au * 8;
    const int brow = tid >> 2;
    const int bu   = tid & 3;
    const uint32_t bcd = swz(brow, bu);
    const size_t boff = (size_t)(blockN + brow) * PD + bu * 8;

    const int mx = lane >> 3;
    const int lr = lane & 7;
    const int rA = (mx & 1) * 8 + lr;
    const int uA = mx >> 1;
    const int rB = (mx >> 1) * 8 + lr;
    const int uB = mx & 1;
    const uint32_t offA0 = (uint32_t)(warpM + rA) * 64 + ((0 + uA) ^ ((rA >> 1) & 3)) * 16;
    const uint32_t offA1 = (uint32_t)(warpM + rA) * 64 + ((2 + uA) ^ ((rA >> 1) & 3)) * 16;
    const uint32_t offB0 = (uint32_t)(warpN + rB) * 64 + ((0 + uB) ^ ((rB >> 1) & 3)) * 16;
    const uint32_t offB1 = (uint32_t)(warpN + rB) * 64 + ((2 + uB) ^ ((rB >> 1) & 3)) * 16;

    float acc[2][4][4];
#pragma unroll
    for (int mt = 0; mt < 2; mt++)
#pragma unroll
        for (int nt = 0; nt < 4; nt++)
#pragma unroll
            for (int j = 0; j < 4; j++) acc[mt][nt][j] = 0.0f;

    auto issue = [&](int chunk, int stage) {
        const int kt = chunk * GBK;
        const uint32_t sd = sbase + stage * STAGEB;
        CP16(sd + acd0, A + aoff + kt);
        CP16(sd + acd1, A + aoff + kt + 8);
        CP16(sd + ATILEB + bcd, B + boff + kt);
    };

    issue(0, 0); CP_COMMIT();
    issue(1, 1); CP_COMMIT();
    issue(2, 2); CP_COMMIT();

    for (int c = 0; c < NITER; c++) {
        CP_WAIT(2);
        __syncthreads();

        if (c + 3 < NITER) issue(c + 3, (c + 3) & 3);
        CP_COMMIT();

        const uint32_t sb = sbase + (c & 3) * STAGEB;

#pragma unroll
        for (int hk = 0; hk < 2; hk++) {
            const uint32_t oA = hk ? offA1 : offA0;
            const uint32_t oB = hk ? offB1 : offB0;
            uint32_t ah[2][4];
#pragma unroll
            for (int mt = 0; mt < 2; mt++)
                LDSM4(ah[mt], sb + oA + mt * 1024);
#pragma unroll
            for (int np = 0; np < 2; np++) {
                uint32_t bh[4];
                LDSM4(bh, sb + ATILEB + oB + np * 1024);
#pragma unroll
                for (int sub = 0; sub < 2; sub++) {
                    const int nt = np * 2 + sub;
#pragma unroll
                    for (int mt = 0; mt < 2; mt++)
                        MMA16816(acc[mt][nt], ah[mt], bh[sub * 2], bh[sub * 2 + 1]);
                }
            }
        }
        __syncthreads();
    }

    const int g  = lane >> 2;
    const int tg = lane & 3;
#pragma unroll
    for (int mt = 0; mt < 2; mt++) {
#pragma unroll
        for (int nt = 0; nt < 4; nt++) {
            const int row = blockM + warpM + mt * 16 + g;
            const int col = blockN + warpN + nt * 8 + tg * 2;
            const size_t o0 = (size_t)row * PD + col;
            const size_t o1 = (size_t)(row + 8) * PD + col;
            *(__nv_bfloat162*)&Cb[o0] = __floats2bfloat162_rn(acc[mt][nt][0], acc[mt][nt][1]);
            *(__nv_bfloat162*)&Cb[o1] = __floats2bfloat162_rn(acc[mt][nt][2], acc[mt][nt][3]);
        }
    }
}

// ---------------------------------------------------------------------------
// Wc GEMM: Wc[e,d] = sum_m Wo[e,m] * Wi[m,d]   (3-term split-bf16, bf16 out)
//   A = Wo (hi/lo), B = Wi^T (hi/lo, both row-major [d, m]).
//   C = Ahi*Bhi + Ahi*Blo + Alo*Bhi   (drop lo*lo; R4/R5-proven pattern)
// Same 128x64 geometry; grid 8x4 = 32 CTAs (tiny GEMM).
// ---------------------------------------------------------------------------
#define WC_STAGEB (2 * ATILEB + 2 * BTILEB)   // 24576
#define WC_SMEM (STAGES * WC_STAGEB)          // 98304

__global__ __launch_bounds__(256, 1)
void wc_gemm_kernel(const __nv_bfloat16* __restrict__ Ahi, const __nv_bfloat16* __restrict__ Alo,
                    const __nv_bfloat16* __restrict__ Bhi, const __nv_bfloat16* __restrict__ Blo,
                    __nv_bfloat16* __restrict__ Cb)
{
    extern __shared__ __align__(128) char sm[];
    const uint32_t sbase = smem_u32(sm);

    const int tid  = threadIdx.x;
    const int lane = tid & 31;
    const int wid  = tid >> 5;
    const int warpM = (wid & 3) * 32;
    const int warpN = (wid >> 2) * 32;
    const int blockM = blockIdx.y * GBM;
    const int blockN = blockIdx.x * GBN;

    const int arow = tid >> 1;
    const int au   = (tid & 1) * 2;
    const uint32_t acd0 = swz(arow, au);
    const uint32_t acd1 = swz(arow, au + 1);
    const size_t aoff = (size_t)(blockM + arow) * PD + au * 8;
    const int brow = tid >> 2;
    const int bu   = tid & 3;
    const uint32_t bcd = swz(brow, bu);
    const size_t boff = (size_t)(blockN + brow) * PD + bu * 8;

    const int mx = lane >> 3;
    const int lr = lane & 7;
    const int rA = (mx & 1) * 8 + lr;
    const int uA = mx >> 1;
    const int rB = (mx >> 1) * 8 + lr;
    const int uB = mx & 1;
    const uint32_t offA0 = (uint32_t)(warpM + rA) * 64 + ((0 + uA) ^ ((rA >> 1) & 3)) * 16;
    const uint32_t offA1 = (uint32_t)(warpM + rA) * 64 + ((2 + uA) ^ ((rA >> 1) & 3)) * 16;
    const uint32_t offB0 = (uint32_t)(warpN + rB) * 64 + ((0 + uB) ^ ((rB >> 1) & 3)) * 16;
    const uint32_t offB1 = (uint32_t)(warpN + rB) * 64 + ((2 + uB) ^ ((rB >> 1) & 3)) * 16;

    float acc[2][4][4];
#pragma unroll
    for (int mt = 0; mt < 2; mt++)
#pragma unroll
        for (int nt = 0; nt < 4; nt++)
#pragma unroll
            for (int j = 0; j < 4; j++) acc[mt][nt][j] = 0.0f;

    auto issue = [&](int chunk, int stage) {
        const int kt = chunk * GBK;
        const uint32_t sd = sbase + stage * WC_STAGEB;
        CP16(sd + acd0, Ahi + aoff + kt);
        CP16(sd + acd1, Ahi + aoff + kt + 8);
        CP16(sd + ATILEB + acd0, Alo + aoff + kt);
        CP16(sd + ATILEB + acd1, Alo + aoff + kt + 8);
        CP16(sd + 2 * ATILEB + bcd, Bhi + boff + kt);
        CP16(sd + 2 * ATILEB + BTILEB + bcd, Blo + boff + kt);
    };

    issue(0, 0); CP_COMMIT();
    issue(1, 1); CP_COMMIT();
    issue(2, 2); CP_COMMIT();

    for (int c = 0; c < NITER; c++) {
        CP_WAIT(2);
        __syncthreads();

        if (c + 3 < NITER) issue(c + 3, (c + 3) & 3);
        CP_COMMIT();

        const uint32_t sb = sbase + (c & 3) * WC_STAGEB;

#pragma unroll
        for (int hk = 0; hk < 2; hk++) {
            const uint32_t oA = hk ? offA1 : offA0;
            const uint32_t oB = hk ? offB1 : offB0;
            uint32_t ah[2][4], al[2][4];
#pragma unroll
            for (int mt = 0; mt < 2; mt++) {
                LDSM4(ah[mt], sb + oA + mt * 1024);
                LDSM4(al[mt], sb + ATILEB + oA + mt * 1024);
            }
#pragma unroll
            for (int np = 0; np < 2; np++) {
                uint32_t bh[4], bl[4];
                LDSM4(bh, sb + 2 * ATILEB + oB + np * 1024);
                LDSM4(bl, sb + 2 * ATILEB + BTILEB + oB + np * 1024);
#pragma unroll
                for (int sub = 0; sub < 2; sub++) {
                    const int nt = np * 2 + sub;
#pragma unroll
                    for (int mt = 0; mt < 2; mt++) {
                        MMA16816(acc[mt][nt], ah[mt], bh[sub * 2], bh[sub * 2 + 1]);
                        MMA16816(acc[mt][nt], ah[mt], bl[sub * 2], bl[sub * 2 + 1]);
                        MMA16816(acc[mt][nt], al[mt], bh[sub * 2], bh[sub * 2 + 1]);
                    }
                }
            }
        }
        __syncthreads();
    }

    const int g  = lane >> 2;
    const int tg = lane & 3;
#pragma unroll
    for (int mt = 0; mt < 2; mt++) {
#pragma unroll
        for (int nt = 0; nt < 4; nt++) {
            const int row = blockM + warpM + mt * 16 + g;
            const int col = blockN + warpN + nt * 8 + tg * 2;
            const size_t o0 = (size_t)row * PD + col;
            const size_t o1 = (size_t)(row + 8) * PD + col;
            *(__nv_bfloat162*)&Cb[o0] = __floats2bfloat162_rn(acc[mt][nt][0], acc[mt][nt][1]);
            *(__nv_bfloat162*)&Cb[o1] = __floats2bfloat162_rn(acc[mt][nt][2], acc[mt][nt][3]);
        }
    }
}

// ---------------------------------------------------------------------------
// Prep A: x -> bf16; Wo -> (hi, lo) split. One launch.
// ---------------------------------------------------------------------------
#define NX (MT * PD)      // 2097152
#define NW (PD * PD)      // 262144
#define PREP_THREADS ((NX + NW) / 4)

__global__ __launch_bounds__(256)
void prep_kernel(const float* __restrict__ x,  __nv_bfloat16* __restrict__ xb,
                 const float* __restrict__ Wo, __nv_bfloat16* __restrict__ woh,
                 __nv_bfloat16* __restrict__ wol)
{
    const int t = blockIdx.x * blockDim.x + threadIdx.x;
    const int i = t * 4;
    if (i < NX) {
        const float4 v = *(const float4*)(x + i);
        __align__(8) __nv_bfloat16 h4[4];
        h4[0] = __float2bfloat16(v.x);
        h4[1] = __float2bfloat16(v.y);
        h4[2] = __float2bfloat16(v.z);
        h4[3] = __float2bfloat16(v.w);
        *(uint2*)(xb + i) = *(const uint2*)h4;
    } else {
        const int j = i - NX;
        const float4 v = *(const float4*)(Wo + j);
        float vv[4] = {v.x, v.y, v.z, v.w};
        __align__(8) __nv_bfloat16 h4[4], l4[4];
#pragma unroll
        for (int q = 0; q < 4; q++) {
            h4[q] = __float2bfloat16(vv[q]);
            l4[q] = __float2bfloat16(vv[q] - __bfloat162float(h4[q]));
        }
        *(uint2*)(woh + j) = *(const uint2*)h4;
        *(uint2*)(wol + j) = *(const uint2*)l4;
    }
}

// ---------------------------------------------------------------------------
// Prep B: Wi -> transposed (hi, lo) split.  64x64 smem tiles, grid (8,8).
//   wit[d, m] = Wi[m, d]
// ---------------------------------------------------------------------------
__global__ __launch_bounds__(256)
void wsplit_t_kernel(const float* __restrict__ Wi,
                     __nv_bfloat16* __restrict__ with_, __nv_bfloat16* __restrict__ witl)
{
    __shared__ float ts[64][65];
    const int tid = threadIdx.x;
    const int bx = blockIdx.x * 64;  // d-base (cols of Wi)
    const int by = blockIdx.y * 64;  // m-base (rows of Wi)

#pragma unroll
    for (int j = 0; j < 4; j++) {
        const int idx = tid + j * 256;    // 0..1023
        const int r  = idx >> 4;          // m-local 0..63
        const int c4 = idx & 15;          // float4 index
        const float4 v = *(const float4*)&Wi[(size_t)(by + r) * PD + bx + c4 * 4];
        ts[r][c4 * 4 + 0] = v.x;
        ts[r][c4 * 4 + 1] = v.y;
        ts[r][c4 * 4 + 2] = v.z;
        ts[r][c4 * 4 + 3] = v.w;
    }
    __syncthreads();

#pragma unroll
    for (int j = 0; j < 4; j++) {
        const int idx = tid + j * 256;
        const int r  = idx >> 4;          // d-local 0..63
        const int c4 = idx & 15;          // m-local/4
        __align__(8) __nv_bfloat16 h4[4], l4[4];
#pragma unroll
        for (int q = 0; q < 4; q++) {
            const float v = ts[c4 * 4 + q][r];
            h4[q] = __float2bfloat16(v);
            l4[q] = __float2bfloat16(v - __bfloat162float(h4[q]));
        }
        const size_t o = (size_t)(bx + r) * PD + by + c4 * 4;
        *(uint2*)(with_ + o) = *(const uint2*)h4;
        *(uint2*)(witl + o)  = *(const uint2*)l4;
    }
}

// ---------------------------------------------------------------------------
// Fused softmax + gather + final epilogue:
//   w[s,:] = softmax_k(-dist[s, routes[s,k]])  (warp 0 per block)
//   out[b,s,:] = sum_k w[s,k] * z[b, routes[s,k], :] + b_out + x[b,s,:]  (fp32)
// ---------------------------------------------------------------------------
__global__ __launch_bounds__(128)
void fuse_kernel(const __nv_bfloat16* __restrict__ z, const int* __restrict__ routes,
                 const float* __restrict__ dist, const float* __restrict__ bias,
                 const float* __restrict__ xres, float* __restrict__ out)
{
    const int s   = blockIdx.x;
    const int tid = threadIdx.x;

    __shared__ __align__(8) uint2 wr[PK];   // .x = row*PD*2 (bytes), .y = w bits

    if (tid < 32) {
        const int lane = tid;
        const int r0 = routes[s * PK + lane];
        const int r1 = routes[s * PK + lane + 32];
        const float v0 = -dist[(size_t)s * PS + r0];
        const float v1 = -dist[(size_t)s * PS + r1];

        float m = fmaxf(v0, v1);
#pragma unroll
        for (int off = 16; off > 0; off >>= 1)
            m = fmaxf(m, __shfl_xor_sync(0xFFFFFFFFu, m, off));

        const float e0 = __expf(v0 - m);
        const float e1 = __expf(v1 - m);
        float sum = e0 + e1;
#pragma unroll
        for (int off = 16; off > 0; off >>= 1)
            sum += __shfl_xor_sync(0xFFFFFFFFu, sum, off);
        const float inv = 1.0f / sum;

        wr[lane]      = make_uint2((uint32_t)r0 * (PD * 2), __float_as_uint(e0 * inv));
        wr[lane + 32] = make_uint2((uint32_t)r1 * (PD * 2), __float_as_uint(e1 * inv));
    }
    __syncthreads();

    const int b = tid >> 6;
    const int t = tid & 63;
    const char* zb = (const char*)(z + (size_t)b * PS * PD) + t * 16;   // col = t*8

    uint64_t a0 = 0, a1 = 0, a2 = 0, a3 = 0;

#pragma unroll
    for (int k = 0; k < PK; k++) {
        const uint2 e = wr[k];
        const uint4 v = *(const uint4*)(zb + e.x);
        uint64_t wk2;
        asm("mov.b64 %0, {%1, %1};" : "=l"(wk2) : "r"(e.y));
        CVT_FMA2(a0, v.x, wk2);
        CVT_FMA2(a1, v.y, wk2);
        CVT_FMA2(a2, v.z, wk2);
        CVT_FMA2(a3, v.w, wk2);
    }

    float r0, r1, r2, r3, r4, r5, r6, r7;
    asm("mov.b64 {%0, %1}, %2;" : "=f"(r0), "=f"(r1) : "l"(a0));
    asm("mov.b64 {%0, %1}, %2;" : "=f"(r2), "=f"(r3) : "l"(a1));
    asm("mov.b64 {%0, %1}, %2;" : "=f"(r4), "=f"(r5) : "l"(a2));
    asm("mov.b64 {%0, %1}, %2;" : "=f"(r6), "=f"(r7) : "l"(a3));

    const int col = t * 8;
    const size_t o = ((size_t)b * PS + s) * PD + col;
    const float4 bb0 = *(const float4*)&bias[col];
    const float4 bb1 = *(const float4*)&bias[col + 4];
    const float4 x0  = *(const float4*)&xres[o];
    const float4 x1  = *(const float4*)&xres[o + 4];

    float4 w0, w1;
    w0.x = r0 + bb0.x + x0.x;  w0.y = r1 + bb0.y + x0.y;
    w0.z = r2 + bb0.z + x0.z;  w0.w = r3 + bb0.w + x0.w;
    w1.x = r4 + bb1.x + x1.x;  w1.y = r5 + bb1.y + x1.y;
    w1.z = r6 + bb1.z + x1.z;  w1.w = r7 + bb1.w + x1.w;
    *(float4*)&out[o]     = w0;
    *(float4*)&out[o + 4] = w1;
}

// ---------------------------------------------------------------------------
// kernel_launch
// Inputs: 0: x (B,S,D) f32 | 1: routes (S,K) i32 | 2: distances (S,S) f32
//         3: W_in (D,D) f32 | 4: W_out (D,D) f32 | 5: b_out (D,) f32
// ---------------------------------------------------------------------------
extern "C" void kernel_launch(void* const* d_in, const int* in_sizes, int n_in,
                              void* d_out, int out_size)
{
    const float* x      = (const float*)d_in[0];
    const int*   routes = (const int*)  d_in[1];
    const float* dist   = (const float*)d_in[2];
    const float* W_in   = (const float*)d_in[3];
    const float* W_out  = (const float*)d_in[4];
    const float* b_out  = (const float*)d_in[5];
    float*       out    = (float*)d_out;

    __nv_bfloat16 *xb, *zb, *woh, *wol, *with_, *witl, *wcb;
    cudaGetSymbolAddress((void**)&xb,    g_x_bf);
    cudaGetSymbolAddress((void**)&zb,    g_z_bf);
    cudaGetSymbolAddress((void**)&woh,   g_wo_hi);
    cudaGetSymbolAddress((void**)&wol,   g_wo_lo);
    cudaGetSymbolAddress((void**)&with_, g_wit_hi);
    cudaGetSymbolAddress((void**)&witl,  g_wit_lo);
    cudaGetSymbolAddress((void**)&wcb,   g_wc_bf);

    static bool attr_set = false;
    if (!attr_set) {
        cudaFuncSetAttribute((const void*)mma_gemm_kernel,
                             cudaFuncAttributeMaxDynamicSharedMemorySize, GEMM_SMEM);
        cudaFuncSetAttribute((const void*)wc_gemm_kernel,
                             cudaFuncAttributeMaxDynamicSharedMemorySize, WC_SMEM);
        attr_set = true;
    }

    // 0a) prep: x -> bf16, Wo -> hi/lo
    prep_kernel<<<PREP_THREADS / 256, 256>>>(x, xb, W_out, woh, wol);

    // 0b) Wi -> transposed hi/lo
    {
        dim3 grid(PD / 64, PD / 64);   // 8 x 8
        wsplit_t_kernel<<<grid, 256>>>(W_in, with_, witl);
    }

    // 1) Wc = Wo @ Wi  (3-term split-bf16, tiny GEMM)
    {
        dim3 grid(PD / GBN, PD / GBM);   // 8 x 4 = 32 CTAs
        wc_gemm_kernel<<<grid, 256, WC_SMEM>>>(woh, wol, with_, witl, wcb);
    }

    // 2) z = x @ Wc^T   (single big GEMM, bf16 out)
    {
        dim3 grid(PD / GBN, MT / GBM);   // 8 x 32 = 256 CTAs
        mma_gemm_kernel<<<grid, 256, GEMM_SMEM>>>(xb, wcb, zb);
    }

    // 3) softmax + gather + bias/residual epilogue -> out (fp32)
    fuse_kernel<<<PS, 128>>>(zb, routes, dist, b_out, x, out);
}